// round 9
// baseline (speedup 1.0000x reference)
#include <cuda_runtime.h>
#include <cuda_bf16.h>
#include <cuda_fp16.h>
#include <cstdint>

#define N_NODES 50000
#define N_EDGES 800000
#define D 128
#define N_LAYERS 3
#define N_GRAPHS 512
#define ND (N_NODES * D)

#define SCAN_BLK 512
#define SCAN_NBLK ((N_NODES + SCAN_BLK - 1) / SCAN_BLK)   // 98

#define FRAG4_PER_LAYER (D * D / 2)   // 8192 float4s per layer (hi+lo interleaved)

// ---------------- scratch (device globals; no allocation allowed) ----------------
__device__ float  g_h[ND];                  // post-GEMM features (fp32)
__device__ __half g_hh[ND];                 // post-GEMM features (fp16, gather source)
__device__ float  g_x[ND];                  // layer output buffer
__device__ float4 g_wf[N_LAYERS * FRAG4_PER_LAYER];  // W frags: (bh0,bh1,bl0,bl1)
__device__ float  g_dis[N_NODES];           // deg^{-1/2} (incl. self-loop)
__device__ int    g_deg[N_NODES];           // in-degree (edges only)
__device__ int    g_cur[N_NODES];           // placement cursor
__device__ int    g_off[N_NODES + 1];       // CSR offsets (by dst)
__device__ int    g_bsum[SCAN_NBLK];        // scan block sums
__device__ float2 g_em[N_EDGES];            // per-slot: (src as int bits, norm)
__device__ float  g_gsum[N_GRAPHS];
__device__ int    g_gcnt[N_GRAPHS];

// ---------------- tf32 split helper ----------------
__device__ __forceinline__ void tf32_split(float v, uint32_t& hi, uint32_t& lo) {
    asm("cvt.rna.tf32.f32 %0, %1;" : "=r"(hi) : "f"(v));
    float r = v - __uint_as_float(hi);
    asm("cvt.rna.tf32.f32 %0, %1;" : "=r"(lo) : "f"(r));
}

#define MMA_TF32(c, a0, a1, a2, a3, b0, b1) \
    asm volatile("mma.sync.aligned.m16n8k8.row.col.f32.tf32.tf32.f32 " \
        "{%0,%1,%2,%3}, {%4,%5,%6,%7}, {%8,%9}, {%0,%1,%2,%3};" \
        : "+f"(c[0]), "+f"(c[1]), "+f"(c[2]), "+f"(c[3]) \
        : "r"(a0), "r"(a1), "r"(a2), "r"(a3), "r"(b0), "r"(b1))

// ---------------- zero ----------------
__global__ void zero_misc_k() {
    int i = blockIdx.x * blockDim.x + threadIdx.x;
    if (i < N_NODES) { g_deg[i] = 0; g_cur[i] = 0; }
    if (i < N_GRAPHS) { g_gsum[i] = 0.f; g_gcnt[i] = 0; }
}

// ---------------- W -> interleaved tf32 split fragments ----------------
__global__ void wfrag_k(const float* __restrict__ Ws) {
    int i = blockIdx.x * blockDim.x + threadIdx.x;
    if (i >= N_LAYERS * D * D) return;
    int l = i / (D * D);
    int rem = i - l * (D * D);
    int o = rem / D;           // Ws[l][o][k]: output col
    int k = rem - o * D;       // reduction index
    uint32_t hi, lo;
    tf32_split(Ws[i], hi, lo);
    int k0 = k >> 3, kin = k & 7;
    int tg = kin & 3, half = kin >> 2;
    int nt = o >> 3, gg = o & 7;
    int lane = gg * 4 + tg;
    int idx4 = (k0 * 16 + nt) * 32 + lane;            // float4 index within layer
    float* base = (float*)(g_wf + l * FRAG4_PER_LAYER + idx4);
    base[half]     = __uint_as_float(hi);
    base[2 + half] = __uint_as_float(lo);
}

// ---------------- degree histogram ----------------
__global__ void deg_k(const int* __restrict__ ei) {
    int e = blockIdx.x * blockDim.x + threadIdx.x;
    if (e >= N_EDGES) return;
    atomicAdd(&g_deg[ei[N_EDGES + e]], 1);
}

// ---------------- scan1 (also computes dis) ----------------
__global__ void scan1_k() {
    __shared__ int sm[SCAN_BLK];
    int tid = threadIdx.x;
    int gid = blockIdx.x * SCAN_BLK + tid;
    int v = 0;
    if (gid < N_NODES) {
        v = g_deg[gid];
        g_dis[gid] = rsqrtf((float)(v + 1));   // +1 self loop
    }
    sm[tid] = v;
    __syncthreads();
    #pragma unroll
    for (int o = 1; o < SCAN_BLK; o <<= 1) {
        int t = (tid >= o) ? sm[tid - o] : 0;
        __syncthreads();
        sm[tid] += t;
        __syncthreads();
    }
    if (gid < N_NODES) g_off[gid] = sm[tid] - v;   // exclusive, block-local
    if (tid == SCAN_BLK - 1) g_bsum[blockIdx.x] = sm[tid];
}
__global__ void scan2_k() {
    if (threadIdx.x == 0) {
        int run = 0;
        for (int i = 0; i < SCAN_NBLK; i++) {
            int t = g_bsum[i];
            g_bsum[i] = run;
            run += t;
        }
    }
}
__global__ void scan3_k() {
    int gid = blockIdx.x * blockDim.x + threadIdx.x;
    if (gid < N_NODES) g_off[gid] += g_bsum[gid / SCAN_BLK];
    if (gid == 0) g_off[N_NODES] = N_EDGES;
}

// ---------------- counting-sort placement: group edges by dst ----------------
__global__ void place_k(const int* __restrict__ ei) {
    int e = blockIdx.x * blockDim.x + threadIdx.x;
    if (e >= N_EDGES) return;
    int r = ei[e];
    int c = ei[N_EDGES + e];
    int idx = g_off[c] + atomicAdd(&g_cur[c], 1);
    g_em[idx] = make_float2(__int_as_float(r), g_dis[r] * g_dis[c]);
}

// ---------------- tensor-core GEMM: H = X @ W^T via split-tf32 (3 mma) ----------------
// Writes fp32 H (self-loop path) AND fp16 HH (gather source).
#define XS_STRIDE 132
__global__ void __launch_bounds__(256)
gemm_tc_k(const float* __restrict__ X, const float4* __restrict__ Fr,
          float* __restrict__ H, __half* __restrict__ HH, int n) {
    extern __shared__ float sm[];
    float* xs = sm;                        // [128][132]

    int tid = threadIdx.x;
    int row0 = blockIdx.x * 128;

    // load X tile into padded smem (float4 coalesced)
    #pragma unroll
    for (int it = 0; it < 16; it++) {
        int i = tid + it * 256;            // 4096 float4s
        int r = i >> 5;
        int c4 = (i & 31) << 2;
        float4 v = make_float4(0.f, 0.f, 0.f, 0.f);
        int rg = row0 + r;
        if (rg < n) v = *(const float4*)(X + rg * D + c4);
        *(float4*)(xs + r * XS_STRIDE + c4) = v;
    }
    __syncthreads();

    int wid = tid >> 5;
    int lane = tid & 31;
    int g = lane >> 2, tig = lane & 3;
    int warpRow = wid * 16;

    float acc[16][4];
    #pragma unroll
    for (int nt = 0; nt < 16; nt++) {
        acc[nt][0] = 0.f; acc[nt][1] = 0.f; acc[nt][2] = 0.f; acc[nt][3] = 0.f;
    }

    const float* rowA0 = xs + (warpRow + g) * XS_STRIDE;
    const float* rowA1 = xs + (warpRow + g + 8) * XS_STRIDE;

    #pragma unroll 2
    for (int k0 = 0; k0 < 16; k0++) {
        int k = k0 * 8;
        float a0f = rowA0[k + tig];
        float a1f = rowA1[k + tig];
        float a2f = rowA0[k + tig + 4];
        float a3f = rowA1[k + tig + 4];
        uint32_t ah0, ah1, ah2, ah3, al0, al1, al2, al3;
        tf32_split(a0f, ah0, al0);
        tf32_split(a1f, ah1, al1);
        tf32_split(a2f, ah2, al2);
        tf32_split(a3f, ah3, al3);

        const float4* bp = Fr + (k0 * 16) * 32 + lane;

        #pragma unroll
        for (int nt = 0; nt < 16; nt++) {
            float4 f = __ldg(bp + nt * 32);
            uint32_t bh0 = __float_as_uint(f.x), bh1 = __float_as_uint(f.y);
            uint32_t bl0 = __float_as_uint(f.z), bl1 = __float_as_uint(f.w);
            MMA_TF32(acc[nt], ah0, ah1, ah2, ah3, bh0, bh1);
            MMA_TF32(acc[nt], ah0, ah1, ah2, ah3, bl0, bl1);
            MMA_TF32(acc[nt], al0, al1, al2, al3, bh0, bh1);
        }
    }

    // store fp32 + fp16: c0,c1 -> row g, cols 2tig,2tig+1; c2,c3 -> row g+8
    int r1 = row0 + warpRow + g;
    int r2 = r1 + 8;
    #pragma unroll
    for (int nt = 0; nt < 16; nt++) {
        int col = nt * 8 + tig * 2;
        if (r1 < n) {
            *(float2*)(H + r1 * D + col) = make_float2(acc[nt][0], acc[nt][1]);
            *(__half2*)(HH + r1 * D + col) = __floats2half2_rn(acc[nt][0], acc[nt][1]);
        }
        if (r2 < n) {
            *(float2*)(H + r2 * D + col) = make_float2(acc[nt][2], acc[nt][3]);
            *(__half2*)(HH + r2 * D + col) = __floats2half2_rn(acc[nt][2], acc[nt][3]);
        }
    }
}

// ---------------- fused gather (fp16 msgs) + self-loop + bias + relu ----------------
// one warp per destination node; each lane owns 4 features (8 B fp16 per edge row)
__device__ __forceinline__ float2 h2f2(uint32_t u) {
    return __half22float2(*(__half2*)&u);
}

__global__ void gather_k(const float* __restrict__ bias) {
    int gt = blockIdx.x * blockDim.x + threadIdx.x;
    int c = gt >> 5;
    int lane = gt & 31;
    if (c >= N_NODES) return;

    int s = g_off[c];
    int e = g_off[c + 1];
    float4 acc = make_float4(0.f, 0.f, 0.f, 0.f);

    const __half* hh = g_hh;
    int i = s;
    for (; i + 4 <= e; i += 4) {
        float2 m0 = g_em[i + 0];
        float2 m1 = g_em[i + 1];
        float2 m2 = g_em[i + 2];
        float2 m3 = g_em[i + 3];
        uint2 u0 = *(const uint2*)(hh + (size_t)__float_as_int(m0.x) * D + lane * 4);
        uint2 u1 = *(const uint2*)(hh + (size_t)__float_as_int(m1.x) * D + lane * 4);
        uint2 u2 = *(const uint2*)(hh + (size_t)__float_as_int(m2.x) * D + lane * 4);
        uint2 u3 = *(const uint2*)(hh + (size_t)__float_as_int(m3.x) * D + lane * 4);
        float2 a0 = h2f2(u0.x), b0 = h2f2(u0.y);
        float2 a1 = h2f2(u1.x), b1 = h2f2(u1.y);
        float2 a2 = h2f2(u2.x), b2 = h2f2(u2.y);
        float2 a3 = h2f2(u3.x), b3 = h2f2(u3.y);
        acc.x += m0.y * a0.x + m1.y * a1.x + m2.y * a2.x + m3.y * a3.x;
        acc.y += m0.y * a0.y + m1.y * a1.y + m2.y * a2.y + m3.y * a3.y;
        acc.z += m0.y * b0.x + m1.y * b1.x + m2.y * b2.x + m3.y * b3.x;
        acc.w += m0.y * b0.y + m1.y * b1.y + m2.y * b2.y + m3.y * b3.y;
    }
    for (; i < e; i++) {
        float2 m = g_em[i];
        uint2 u = *(const uint2*)(hh + (size_t)__float_as_int(m.x) * D + lane * 4);
        float2 a = h2f2(u.x), b = h2f2(u.y);
        acc.x += m.y * a.x; acc.y += m.y * a.y;
        acc.z += m.y * b.x; acc.w += m.y * b.y;
    }

    float d = g_dis[c];
    float d2 = d * d;
    float4 h = *(const float4*)(g_h + (size_t)c * D + lane * 4);
    float4 b = ((const float4*)bias)[lane];
    float4 o;
    o.x = fmaxf(acc.x + d2 * h.x + b.x, 0.f);
    o.y = fmaxf(acc.y + d2 * h.y + b.y, 0.f);
    o.z = fmaxf(acc.z + d2 * h.z + b.z, 0.f);
    o.w = fmaxf(acc.w + d2 * h.w + b.w, 0.f);
    *(float4*)(g_x + (size_t)c * D + lane * 4) = o;
}

// ---------------- pooling ----------------
__global__ void pool_k(const int* __restrict__ batch, const float* __restrict__ lw) {
    int gt = blockIdx.x * blockDim.x + threadIdx.x;
    int node = gt >> 5;
    int lane = gt & 31;
    if (node >= N_NODES) return;
    float4 xv = ((const float4*)g_x)[node * 32 + lane];
    float4 wv = ((const float4*)lw)[lane];
    float s = xv.x * wv.x + xv.y * wv.y + xv.z * wv.z + xv.w * wv.w;
    #pragma unroll
    for (int o = 16; o > 0; o >>= 1) s += __shfl_xor_sync(0xFFFFFFFFu, s, o);
    if (lane == 0) {
        int g = batch[node];
        atomicAdd(&g_gsum[g], s);
        atomicAdd(&g_gcnt[g], 1);
    }
}

__global__ void final_k(const float* __restrict__ lb, float* __restrict__ out) {
    int g = blockIdx.x * blockDim.x + threadIdx.x;
    if (g >= N_GRAPHS) return;
    float c = fmaxf((float)g_gcnt[g], 1.0f);
    out[g] = g_gsum[g] / c + lb[0];
}

// ---------------- launcher ----------------
extern "C" void kernel_launch(void* const* d_in, const int* in_sizes, int n_in,
                              void* d_out, int out_size) {
    const float* x    = (const float*)d_in[0];
    const int*   ei   = (const int*)d_in[1];    // int32 (JAX x64 disabled)
    const int*   bat  = (const int*)d_in[2];
    const float* Ws   = (const float*)d_in[3];
    const float* bs   = (const float*)d_in[4];
    const float* lw   = (const float*)d_in[5];
    const float* lb   = (const float*)d_in[6];
    float*       out  = (float*)d_out;

    const int gemm_smem = (128 * XS_STRIDE) * (int)sizeof(float);   // 67.6 KB

    static bool attr_set = false;
    if (!attr_set) {
        cudaFuncSetAttribute(gemm_tc_k, cudaFuncAttributeMaxDynamicSharedMemorySize,
                             gemm_smem);
        attr_set = true;
    }

    float *h_p, *x_p;
    __half *hh_p;
    float4 *wf_p;
    cudaGetSymbolAddress((void**)&h_p,  g_h);
    cudaGetSymbolAddress((void**)&hh_p, g_hh);
    cudaGetSymbolAddress((void**)&x_p,  g_x);
    cudaGetSymbolAddress((void**)&wf_p, g_wf);

    // prep
    zero_misc_k<<<(N_NODES + 255) / 256, 256>>>();
    wfrag_k<<<(N_LAYERS * D * D + 255) / 256, 256>>>(Ws);
    deg_k<<<(N_EDGES + 255) / 256, 256>>>(ei);
    scan1_k<<<SCAN_NBLK, SCAN_BLK>>>();
    scan2_k<<<1, 32>>>();
    scan3_k<<<(N_NODES + 255) / 256, 256>>>();
    place_k<<<(N_EDGES + 255) / 256, 256>>>(ei);

    // layers
    const int gemm_blocks = (N_NODES + 127) / 128;
    const int gather_blocks = (N_NODES * 32 + 255) / 256;

    for (int l = 0; l < N_LAYERS; l++) {
        const float* xin = (l == 0) ? x : x_p;
        gemm_tc_k<<<gemm_blocks, 256, gemm_smem>>>(
            xin, wf_p + l * FRAG4_PER_LAYER, h_p, hh_p, N_NODES);
        gather_k<<<gather_blocks, 256>>>(bs + l * D);
    }

    // pooling + output
    pool_k<<<(N_NODES * 32 + 255) / 256, 256>>>(bat, lw);
    final_k<<<(N_GRAPHS + 255) / 256, 256>>>(lb, out);
}

// round 10
// speedup vs baseline: 1.2869x; 1.2869x over previous
#include <cuda_runtime.h>
#include <cuda_bf16.h>
#include <cuda_fp16.h>
#include <cstdint>

#define N_NODES 50000
#define N_EDGES 800000
#define D 128
#define N_LAYERS 3
#define N_GRAPHS 512
#define ND (N_NODES * D)

#define SCAN_BLK 512
#define SCAN_NBLK ((N_NODES + SCAN_BLK - 1) / SCAN_BLK)   // 98

// fp16 fragments: 8 ksteps x 16 nt x 32 lanes x 8 halves (bh0,bh1,bl0,bl1 as half2s)
#define KSTEPS (D / 16)                       // 8
#define FRAGH_PER_LAYER (KSTEPS * 16 * 32 * 8)   // 32768 halves = 64KB

// ---------------- scratch (device globals; no allocation allowed) ----------------
__device__ float  g_h[ND];                  // post-GEMM features
__device__ float  g_x[ND];                  // layer output buffer
__device__ __half g_wfh[N_LAYERS * FRAGH_PER_LAYER];  // W split-fp16 fragments
__device__ float  g_dis[N_NODES];           // deg^{-1/2} (incl. self-loop)
__device__ int    g_deg[N_NODES];           // in-degree (edges only)
__device__ int    g_cur[N_NODES];           // placement cursor
__device__ int    g_off[N_NODES + 1];       // CSR offsets (by dst)
__device__ int    g_bsum[SCAN_NBLK];        // scan block sums
__device__ float2 g_em[N_EDGES];            // per-slot: (src as int bits, norm)
__device__ float  g_gsum[N_GRAPHS];
__device__ int    g_gcnt[N_GRAPHS];

#define MMA_F16(c, a0, a1, a2, a3, b0, b1) \
    asm volatile("mma.sync.aligned.m16n8k16.row.col.f32.f16.f16.f32 " \
        "{%0,%1,%2,%3}, {%4,%5,%6,%7}, {%8,%9}, {%0,%1,%2,%3};" \
        : "+f"(c[0]), "+f"(c[1]), "+f"(c[2]), "+f"(c[3]) \
        : "r"(a0), "r"(a1), "r"(a2), "r"(a3), "r"(b0), "r"(b1))

// ---------------- zero ----------------
__global__ void zero_misc_k() {
    int i = blockIdx.x * blockDim.x + threadIdx.x;
    if (i < N_NODES) { g_deg[i] = 0; g_cur[i] = 0; }
    if (i < N_GRAPHS) { g_gsum[i] = 0.f; g_gcnt[i] = 0; }
}

// ---------------- W -> split-fp16 fragments (B-fragment order, m16n8k16) ----------------
// For (l, o, k): kstep=k/16, kin=k%16. b0 covers kin 0-7, b1 covers kin 8-15.
// half2 low element = even kin. lane = (o%8)*4 + (kin%8)/2.
// 8-half slot layout: [bh0.lo,bh0.hi, bh1.lo,bh1.hi, bl0.lo,bl0.hi, bl1.lo,bl1.hi]
__global__ void wfrag_k(const float* __restrict__ Ws) {
    int i = blockIdx.x * blockDim.x + threadIdx.x;
    if (i >= N_LAYERS * D * D) return;
    int l = i / (D * D);
    int rem = i - l * (D * D);
    int o = rem / D;           // Ws[l][o][k]
    int k = rem - o * D;
    float v = Ws[i];
    __half hi = __float2half_rn(v);
    __half lo = __float2half_rn(v - __half2float(hi));
    int kstep = k >> 4, kin = k & 15;
    int tig = (kin & 7) >> 1;
    int hpos = kin & 1;
    int b01 = kin >> 3;        // 0 -> b0, 1 -> b1
    int nt = o >> 3, gg = o & 7;
    int lane = gg * 4 + tig;
    size_t base = ((((size_t)l * KSTEPS + kstep) * 16 + nt) * 32 + lane) * 8;
    g_wfh[base + b01 * 2 + hpos]     = hi;
    g_wfh[base + 4 + b01 * 2 + hpos] = lo;
}

// ---------------- degree histogram ----------------
__global__ void deg_k(const int* __restrict__ ei) {
    int e = blockIdx.x * blockDim.x + threadIdx.x;
    if (e >= N_EDGES) return;
    atomicAdd(&g_deg[ei[N_EDGES + e]], 1);
}

// ---------------- scan1 (also computes dis) ----------------
__global__ void scan1_k() {
    __shared__ int sm[SCAN_BLK];
    int tid = threadIdx.x;
    int gid = blockIdx.x * SCAN_BLK + tid;
    int v = 0;
    if (gid < N_NODES) {
        v = g_deg[gid];
        g_dis[gid] = rsqrtf((float)(v + 1));   // +1 self loop
    }
    sm[tid] = v;
    __syncthreads();
    #pragma unroll
    for (int o = 1; o < SCAN_BLK; o <<= 1) {
        int t = (tid >= o) ? sm[tid - o] : 0;
        __syncthreads();
        sm[tid] += t;
        __syncthreads();
    }
    if (gid < N_NODES) g_off[gid] = sm[tid] - v;
    if (tid == SCAN_BLK - 1) g_bsum[blockIdx.x] = sm[tid];
}
__global__ void scan2_k() {
    if (threadIdx.x == 0) {
        int run = 0;
        for (int i = 0; i < SCAN_NBLK; i++) {
            int t = g_bsum[i];
            g_bsum[i] = run;
            run += t;
        }
    }
}
__global__ void scan3_k() {
    int gid = blockIdx.x * blockDim.x + threadIdx.x;
    if (gid < N_NODES) g_off[gid] += g_bsum[gid / SCAN_BLK];
    if (gid == 0) g_off[N_NODES] = N_EDGES;
}

// ---------------- counting-sort placement ----------------
__global__ void place_k(const int* __restrict__ ei) {
    int e = blockIdx.x * blockDim.x + threadIdx.x;
    if (e >= N_EDGES) return;
    int r = ei[e];
    int c = ei[N_EDGES + e];
    int idx = g_off[c] + atomicAdd(&g_cur[c], 1);
    g_em[idx] = make_float2(__int_as_float(r), g_dis[r] * g_dis[c]);
}

// ---------------- tensor-core GEMM: H = X @ W^T via split-fp16 (3 mma, k=16) ----------------
// block: 256 threads (8 warps), 128x128 tile, full K=128 in 8 k-steps.
// Per (kstep, nt): ONE LDG.128 delivers (bh0,bh1,bl0,bl1); 3 HMMA.
#define XS_STRIDE 132
__global__ void __launch_bounds__(256)
gemm_tc_k(const float* __restrict__ X, const uint4* __restrict__ Fr,
          float* __restrict__ H, int n) {
    extern __shared__ float sm[];
    float* xs = sm;                        // [128][132]

    int tid = threadIdx.x;
    int row0 = blockIdx.x * 128;

    #pragma unroll
    for (int it = 0; it < 16; it++) {
        int i = tid + it * 256;            // 4096 float4s
        int r = i >> 5;
        int c4 = (i & 31) << 2;
        float4 v = make_float4(0.f, 0.f, 0.f, 0.f);
        int rg = row0 + r;
        if (rg < n) v = *(const float4*)(X + rg * D + c4);
        *(float4*)(xs + r * XS_STRIDE + c4) = v;
    }
    __syncthreads();

    int wid = tid >> 5;
    int lane = tid & 31;
    int g = lane >> 2, tig = lane & 3;
    int warpRow = wid * 16;

    float acc[16][4];
    #pragma unroll
    for (int nt = 0; nt < 16; nt++) {
        acc[nt][0] = 0.f; acc[nt][1] = 0.f; acc[nt][2] = 0.f; acc[nt][3] = 0.f;
    }

    const float* rowA0 = xs + (warpRow + g) * XS_STRIDE;
    const float* rowA1 = xs + (warpRow + g + 8) * XS_STRIDE;

    #pragma unroll
    for (int kstep = 0; kstep < KSTEPS; kstep++) {
        int k = kstep * 16;
        // A fragment: a0=[g][k+2tig..+1], a1=[g+8][same], a2=[g][k+8+2tig..+1], a3=[g+8][same]
        float2 f0 = *(const float2*)(rowA0 + k + 2 * tig);
        float2 f1 = *(const float2*)(rowA1 + k + 2 * tig);
        float2 f2 = *(const float2*)(rowA0 + k + 8 + 2 * tig);
        float2 f3 = *(const float2*)(rowA1 + k + 8 + 2 * tig);

        __half2 h0 = __float22half2_rn(f0);
        __half2 h1 = __float22half2_rn(f1);
        __half2 h2 = __float22half2_rn(f2);
        __half2 h3 = __float22half2_rn(f3);
        float2 r0 = __half22float2(h0);
        float2 r1 = __half22float2(h1);
        float2 r2 = __half22float2(h2);
        float2 r3 = __half22float2(h3);
        __half2 l0 = __float22half2_rn(make_float2(f0.x - r0.x, f0.y - r0.y));
        __half2 l1 = __float22half2_rn(make_float2(f1.x - r1.x, f1.y - r1.y));
        __half2 l2 = __float22half2_rn(make_float2(f2.x - r2.x, f2.y - r2.y));
        __half2 l3 = __float22half2_rn(make_float2(f3.x - r3.x, f3.y - r3.y));

        uint32_t ah0 = *(uint32_t*)&h0, ah1 = *(uint32_t*)&h1;
        uint32_t ah2 = *(uint32_t*)&h2, ah3 = *(uint32_t*)&h3;
        uint32_t al0 = *(uint32_t*)&l0, al1 = *(uint32_t*)&l1;
        uint32_t al2 = *(uint32_t*)&l2, al3 = *(uint32_t*)&l3;

        const uint4* bp = Fr + (kstep * 16) * 32 + lane;

        #pragma unroll
        for (int nt = 0; nt < 16; nt++) {
            uint4 f = __ldg(bp + nt * 32);    // (bh0, bh1, bl0, bl1)
            MMA_F16(acc[nt], ah0, ah1, ah2, ah3, f.x, f.y);   // hi * hi
            MMA_F16(acc[nt], ah0, ah1, ah2, ah3, f.z, f.w);   // hi * lo
            MMA_F16(acc[nt], al0, al1, al2, al3, f.x, f.y);   // lo * hi
        }
    }

    // store: c0,c1 -> row g, cols 2tig,2tig+1; c2,c3 -> row g+8
    int r1 = row0 + warpRow + g;
    int r2 = r1 + 8;
    #pragma unroll
    for (int nt = 0; nt < 16; nt++) {
        int col = nt * 8 + tig * 2;
        if (r1 < n) *(float2*)(H + r1 * D + col) = make_float2(acc[nt][0], acc[nt][1]);
        if (r2 < n) *(float2*)(H + r2 * D + col) = make_float2(acc[nt][2], acc[nt][3]);
    }
}

// ---------------- fused gather + self-loop + bias + relu (atomic-free, fp32) ----------------
__global__ void gather_k(const float* __restrict__ bias) {
    int gt = blockIdx.x * blockDim.x + threadIdx.x;
    int c = gt >> 5;
    int lane = gt & 31;
    if (c >= N_NODES) return;

    int s = g_off[c];
    int e = g_off[c + 1];
    float4 acc = make_float4(0.f, 0.f, 0.f, 0.f);

    int i = s;
    for (; i + 4 <= e; i += 4) {
        float2 m0 = g_em[i + 0];
        float2 m1 = g_em[i + 1];
        float2 m2 = g_em[i + 2];
        float2 m3 = g_em[i + 3];
        const float4 v0 = *(const float4*)(g_h + (size_t)__float_as_int(m0.x) * D + lane * 4);
        const float4 v1 = *(const float4*)(g_h + (size_t)__float_as_int(m1.x) * D + lane * 4);
        const float4 v2 = *(const float4*)(g_h + (size_t)__float_as_int(m2.x) * D + lane * 4);
        const float4 v3 = *(const float4*)(g_h + (size_t)__float_as_int(m3.x) * D + lane * 4);
        acc.x += m0.y * v0.x + m1.y * v1.x + m2.y * v2.x + m3.y * v3.x;
        acc.y += m0.y * v0.y + m1.y * v1.y + m2.y * v2.y + m3.y * v3.y;
        acc.z += m0.y * v0.z + m1.y * v1.z + m2.y * v2.z + m3.y * v3.z;
        acc.w += m0.y * v0.w + m1.y * v1.w + m2.y * v2.w + m3.y * v3.w;
    }
    for (; i < e; i++) {
        float2 m = g_em[i];
        const float4 v = *(const float4*)(g_h + (size_t)__float_as_int(m.x) * D + lane * 4);
        acc.x += m.y * v.x; acc.y += m.y * v.y; acc.z += m.y * v.z; acc.w += m.y * v.w;
    }

    float d = g_dis[c];
    float d2 = d * d;
    float4 h = *(const float4*)(g_h + (size_t)c * D + lane * 4);
    float4 b = ((const float4*)bias)[lane];
    float4 o;
    o.x = fmaxf(acc.x + d2 * h.x + b.x, 0.f);
    o.y = fmaxf(acc.y + d2 * h.y + b.y, 0.f);
    o.z = fmaxf(acc.z + d2 * h.z + b.z, 0.f);
    o.w = fmaxf(acc.w + d2 * h.w + b.w, 0.f);
    *(float4*)(g_x + (size_t)c * D + lane * 4) = o;
}

// ---------------- pooling ----------------
__global__ void pool_k(const int* __restrict__ batch, const float* __restrict__ lw) {
    int gt = blockIdx.x * blockDim.x + threadIdx.x;
    int node = gt >> 5;
    int lane = gt & 31;
    if (node >= N_NODES) return;
    float4 xv = ((const float4*)g_x)[node * 32 + lane];
    float4 wv = ((const float4*)lw)[lane];
    float s = xv.x * wv.x + xv.y * wv.y + xv.z * wv.z + xv.w * wv.w;
    #pragma unroll
    for (int o = 16; o > 0; o >>= 1) s += __shfl_xor_sync(0xFFFFFFFFu, s, o);
    if (lane == 0) {
        int g = batch[node];
        atomicAdd(&g_gsum[g], s);
        atomicAdd(&g_gcnt[g], 1);
    }
}

__global__ void final_k(const float* __restrict__ lb, float* __restrict__ out) {
    int g = blockIdx.x * blockDim.x + threadIdx.x;
    if (g >= N_GRAPHS) return;
    float c = fmaxf((float)g_gcnt[g], 1.0f);
    out[g] = g_gsum[g] / c + lb[0];
}

// ---------------- launcher ----------------
extern "C" void kernel_launch(void* const* d_in, const int* in_sizes, int n_in,
                              void* d_out, int out_size) {
    const float* x    = (const float*)d_in[0];
    const int*   ei   = (const int*)d_in[1];    // int32 (JAX x64 disabled)
    const int*   bat  = (const int*)d_in[2];
    const float* Ws   = (const float*)d_in[3];
    const float* bs   = (const float*)d_in[4];
    const float* lw   = (const float*)d_in[5];
    const float* lb   = (const float*)d_in[6];
    float*       out  = (float*)d_out;

    const int gemm_smem = (128 * XS_STRIDE) * (int)sizeof(float);   // 67.6 KB

    static bool attr_set = false;
    if (!attr_set) {
        cudaFuncSetAttribute(gemm_tc_k, cudaFuncAttributeMaxDynamicSharedMemorySize,
                             gemm_smem);
        attr_set = true;
    }

    float *h_p, *x_p;
    __half *wfh_p;
    cudaGetSymbolAddress((void**)&h_p,   g_h);
    cudaGetSymbolAddress((void**)&x_p,   g_x);
    cudaGetSymbolAddress((void**)&wfh_p, g_wfh);

    // prep
    zero_misc_k<<<(N_NODES + 255) / 256, 256>>>();
    wfrag_k<<<(N_LAYERS * D * D + 255) / 256, 256>>>(Ws);
    deg_k<<<(N_EDGES + 255) / 256, 256>>>(ei);
    scan1_k<<<SCAN_NBLK, SCAN_BLK>>>();
    scan2_k<<<1, 32>>>();
    scan3_k<<<(N_NODES + 255) / 256, 256>>>();
    place_k<<<(N_EDGES + 255) / 256, 256>>>(ei);

    // layers
    const int gemm_blocks = (N_NODES + 127) / 128;
    const int gather_blocks = (N_NODES * 32 + 255) / 256;

    for (int l = 0; l < N_LAYERS; l++) {
        const float* xin = (l == 0) ? x : x_p;
        gemm_tc_k<<<gemm_blocks, 256, gemm_smem>>>(
            xin, (const uint4*)(wfh_p + (size_t)l * FRAGH_PER_LAYER), h_p, N_NODES);
        gather_k<<<gather_blocks, 256>>>(bs + l * D);
    }

    // pooling + output
    pool_k<<<(N_NODES * 32 + 255) / 256, 256>>>(bat, lw);
    final_k<<<(N_GRAPHS + 255) / 256, 256>>>(lb, out);
}

// round 12
// speedup vs baseline: 1.2959x; 1.0070x over previous
#include <cuda_runtime.h>
#include <cuda_fp16.h>
#include <cstdint>

#define N_NODES 50000
#define N_EDGES 800000
#define D 128
#define N_LAYERS 3
#define N_GRAPHS 512
#define NROWS 50048                     // padded to 391*128 (device globals zero-init)
#define ND (N_NODES * D)
#define NDP (NROWS * D)

#define SCAN_BLK 512
#define SCAN_NBLK ((N_NODES + SCAN_BLK - 1) / SCAN_BLK)   // 98

// fp16 fragments: 8 ksteps x 16 nt x 32 lanes x 8 halves (bh0,bh1,bl0,bl1 as half2s)
#define KSTEPS (D / 16)                       // 8
#define FRAGH_PER_LAYER (KSTEPS * 16 * 32 * 8)   // 32768 halves = 64KB

// ---------------- scratch (device globals; no allocation allowed) ----------------
__device__ float  g_h[NDP];                 // post-GEMM features (fp32), padded
__device__ __half g_xh[NDP];                // layer input, fp16 hi, padded
__device__ __half g_xl[NDP];                // layer input, fp16 lo (residual), padded
__device__ float  g_x[ND];                  // final layer output (pool input)
__device__ __half g_wfh[N_LAYERS * FRAGH_PER_LAYER];  // W split-fp16 fragments
__device__ float  g_dis[N_NODES];
__device__ int    g_deg[N_NODES];
__device__ int    g_cur[N_NODES];
__device__ int    g_off[N_NODES + 1];
__device__ int    g_bsum[SCAN_NBLK];
__device__ float2 g_em[N_EDGES];            // (src as int bits, norm)
__device__ float  g_gsum[N_GRAPHS];
__device__ int    g_gcnt[N_GRAPHS];

#define MMA_F16(c, a0, a1, a2, a3, b0, b1) \
    asm volatile("mma.sync.aligned.m16n8k16.row.col.f32.f16.f16.f32 " \
        "{%0,%1,%2,%3}, {%4,%5,%6,%7}, {%8,%9}, {%0,%1,%2,%3};" \
        : "+f"(c[0]), "+f"(c[1]), "+f"(c[2]), "+f"(c[3]) \
        : "r"(a0), "r"(a1), "r"(a2), "r"(a3), "r"(b0), "r"(b1))

// ---------------- W -> split-fp16 fragments (B-fragment order, m16n8k16) ----------------
__global__ void wfrag_k(const float* __restrict__ Ws) {
    int i = blockIdx.x * blockDim.x + threadIdx.x;
    if (i >= N_LAYERS * D * D) return;
    int l = i / (D * D);
    int rem = i - l * (D * D);
    int o = rem / D;           // Ws[l][o][k]
    int k = rem - o * D;
    float v = Ws[i];
    __half hi = __float2half_rn(v);
    __half lo = __float2half_rn(v - __half2float(hi));
    int kstep = k >> 4, kin = k & 15;
    int tig = (kin & 7) >> 1;
    int hpos = kin & 1;
    int b01 = kin >> 3;        // 0 -> b0, 1 -> b1
    int nt = o >> 3, gg = o & 7;
    int lane = gg * 4 + tig;
    size_t base = ((((size_t)l * KSTEPS + kstep) * 16 + nt) * 32 + lane) * 8;
    g_wfh[base + b01 * 2 + hpos]     = hi;
    g_wfh[base + 4 + b01 * 2 + hpos] = lo;
}

// ---------------- layer-0 input split ----------------
__global__ void conv0_k(const float* __restrict__ X) {
    int i = blockIdx.x * blockDim.x + threadIdx.x;
    if (i >= ND / 2) return;
    float2 v = ((const float2*)X)[i];
    __half hx = __float2half_rn(v.x), hy = __float2half_rn(v.y);
    __half lx = __float2half_rn(v.x - __half2float(hx));
    __half ly = __float2half_rn(v.y - __half2float(hy));
    ((__half2*)g_xh)[i] = __halves2half2(hx, hy);
    ((__half2*)g_xl)[i] = __halves2half2(lx, ly);
}

// ---------------- zero ----------------
__global__ void zero_misc_k() {
    int i = blockIdx.x * blockDim.x + threadIdx.x;
    if (i < N_NODES) { g_deg[i] = 0; g_cur[i] = 0; }
    if (i < N_GRAPHS) { g_gsum[i] = 0.f; g_gcnt[i] = 0; }
}

// ---------------- degree histogram ----------------
__global__ void deg_k(const int* __restrict__ ei) {
    int e = blockIdx.x * blockDim.x + threadIdx.x;
    if (e >= N_EDGES) return;
    atomicAdd(&g_deg[ei[N_EDGES + e]], 1);
}

// ---------------- scan (also computes dis) ----------------
__global__ void scan1_k() {
    __shared__ int sm[SCAN_BLK];
    int tid = threadIdx.x;
    int gid = blockIdx.x * SCAN_BLK + tid;
    int v = 0;
    if (gid < N_NODES) {
        v = g_deg[gid];
        g_dis[gid] = rsqrtf((float)(v + 1));
    }
    sm[tid] = v;
    __syncthreads();
    #pragma unroll
    for (int o = 1; o < SCAN_BLK; o <<= 1) {
        int t = (tid >= o) ? sm[tid - o] : 0;
        __syncthreads();
        sm[tid] += t;
        __syncthreads();
    }
    if (gid < N_NODES) g_off[gid] = sm[tid] - v;
    if (tid == SCAN_BLK - 1) g_bsum[blockIdx.x] = sm[tid];
}
__global__ void scan2_k() {
    if (threadIdx.x == 0) {
        int run = 0;
        for (int i = 0; i < SCAN_NBLK; i++) {
            int t = g_bsum[i];
            g_bsum[i] = run;
            run += t;
        }
    }
}
__global__ void scan3_k() {
    int gid = blockIdx.x * blockDim.x + threadIdx.x;
    if (gid < N_NODES) g_off[gid] += g_bsum[gid / SCAN_BLK];
    if (gid == 0) g_off[N_NODES] = N_EDGES;
}

// ---------------- counting-sort placement ----------------
__global__ void place_k(const int* __restrict__ ei) {
    int e = blockIdx.x * blockDim.x + threadIdx.x;
    if (e >= N_EDGES) return;
    int r = ei[e];
    int c = ei[N_EDGES + e];
    int idx = g_off[c] + atomicAdd(&g_cur[c], 1);
    g_em[idx] = make_float2(__int_as_float(r), g_dis[r] * g_dis[c]);
}

// ---------------- tensor-core GEMM: H = X @ W^T via split-fp16 (3 mma, k=16) ----------
// 256 threads (8 warps), 128x128 tile, K=128 in 8 k-steps. NO smem.
// A fragments: direct LDG.32 from persistent fp16 hi/lo arrays (rows padded+zeroed).
// B fragments: ONE LDG.128 per (kstep,nt) delivers (bh0,bh1,bl0,bl1); L1-resident.
__global__ void __launch_bounds__(256)
gemm_tc_k(const __half* __restrict__ XH, const __half* __restrict__ XL,
          const uint4* __restrict__ Fr, float* __restrict__ H) {
    int tid = threadIdx.x;
    int wid = tid >> 5;
    int lane = tid & 31;
    int g = lane >> 2, tig = lane & 3;
    int r1 = blockIdx.x * 128 + wid * 16 + g;   // rows for c0/c1 (a0/a2)
    int r2 = r1 + 8;                            // rows for c2/c3 (a1/a3)

    const __half* a0p = XH + (size_t)r1 * D + 2 * tig;
    const __half* a1p = XH + (size_t)r2 * D + 2 * tig;
    const __half* l0p = XL + (size_t)r1 * D + 2 * tig;
    const __half* l1p = XL + (size_t)r2 * D + 2 * tig;

    float acc[16][4];
    #pragma unroll
    for (int nt = 0; nt < 16; nt++) {
        acc[nt][0] = 0.f; acc[nt][1] = 0.f; acc[nt][2] = 0.f; acc[nt][3] = 0.f;
    }

    #pragma unroll
    for (int kstep = 0; kstep < KSTEPS; kstep++) {
        int k = kstep * 16;
        uint32_t ah0 = *(const uint32_t*)(a0p + k);
        uint32_t ah1 = *(const uint32_t*)(a1p + k);
        uint32_t ah2 = *(const uint32_t*)(a0p + k + 8);
        uint32_t ah3 = *(const uint32_t*)(a1p + k + 8);
        uint32_t al0 = *(const uint32_t*)(l0p + k);
        uint32_t al1 = *(const uint32_t*)(l1p + k);
        uint32_t al2 = *(const uint32_t*)(l0p + k + 8);
        uint32_t al3 = *(const uint32_t*)(l1p + k + 8);

        const uint4* bp = Fr + (kstep * 16) * 32 + lane;

        #pragma unroll
        for (int nt = 0; nt < 16; nt++) {
            uint4 f = __ldg(bp + nt * 32);    // (bh0, bh1, bl0, bl1)
            MMA_F16(acc[nt], ah0, ah1, ah2, ah3, f.x, f.y);   // hi * hi
            MMA_F16(acc[nt], ah0, ah1, ah2, ah3, f.z, f.w);   // hi * lo
            MMA_F16(acc[nt], al0, al1, al2, al3, f.x, f.y);   // lo * hi
        }
    }

    // store (rows padded -> no guards): c0,c1 -> row r1; c2,c3 -> row r2
    #pragma unroll
    for (int nt = 0; nt < 16; nt++) {
        int col = nt * 8 + tig * 2;
        *(float2*)(H + (size_t)r1 * D + col) = make_float2(acc[nt][0], acc[nt][1]);
        *(float2*)(H + (size_t)r2 * D + col) = make_float2(acc[nt][2], acc[nt][3]);
    }
}

// ---------------- fused gather + self-loop + bias + relu; emits fp16 hi/lo ----------
__global__ void gather_k(const float* __restrict__ bias, int write_f32) {
    int gt = blockIdx.x * blockDim.x + threadIdx.x;
    int c = gt >> 5;
    int lane = gt & 31;
    if (c >= N_NODES) return;

    int s = g_off[c];
    int e = g_off[c + 1];
    float4 acc = make_float4(0.f, 0.f, 0.f, 0.f);

    int i = s;
    for (; i + 4 <= e; i += 4) {
        float2 m0 = g_em[i + 0];
        float2 m1 = g_em[i + 1];
        float2 m2 = g_em[i + 2];
        float2 m3 = g_em[i + 3];
        const float4 v0 = *(const float4*)(g_h + (size_t)__float_as_int(m0.x) * D + lane * 4);
        const float4 v1 = *(const float4*)(g_h + (size_t)__float_as_int(m1.x) * D + lane * 4);
        const float4 v2 = *(const float4*)(g_h + (size_t)__float_as_int(m2.x) * D + lane * 4);
        const float4 v3 = *(const float4*)(g_h + (size_t)__float_as_int(m3.x) * D + lane * 4);
        acc.x += m0.y * v0.x + m1.y * v1.x + m2.y * v2.x + m3.y * v3.x;
        acc.y += m0.y * v0.y + m1.y * v1.y + m2.y * v2.y + m3.y * v3.y;
        acc.z += m0.y * v0.z + m1.y * v1.z + m2.y * v2.z + m3.y * v3.z;
        acc.w += m0.y * v0.w + m1.y * v1.w + m2.y * v2.w + m3.y * v3.w;
    }
    for (; i < e; i++) {
        float2 m = g_em[i];
        const float4 v = *(const float4*)(g_h + (size_t)__float_as_int(m.x) * D + lane * 4);
        acc.x += m.y * v.x; acc.y += m.y * v.y; acc.z += m.y * v.z; acc.w += m.y * v.w;
    }

    float d = g_dis[c];
    float d2 = d * d;
    float4 h = *(const float4*)(g_h + (size_t)c * D + lane * 4);
    float4 b = ((const float4*)bias)[lane];
    float4 o;
    o.x = fmaxf(acc.x + d2 * h.x + b.x, 0.f);
    o.y = fmaxf(acc.y + d2 * h.y + b.y, 0.f);
    o.z = fmaxf(acc.z + d2 * h.z + b.z, 0.f);
    o.w = fmaxf(acc.w + d2 * h.w + b.w, 0.f);

    size_t base = (size_t)c * D + lane * 4;
    __half h0 = __float2half_rn(o.x), h1 = __float2half_rn(o.y);
    __half h2 = __float2half_rn(o.z), h3 = __float2half_rn(o.w);
    *(__half2*)(g_xh + base)     = __halves2half2(h0, h1);
    *(__half2*)(g_xh + base + 2) = __halves2half2(h2, h3);
    __half l0 = __float2half_rn(o.x - __half2float(h0));
    __half l1 = __float2half_rn(o.y - __half2float(h1));
    __half l2 = __float2half_rn(o.z - __half2float(h2));
    __half l3 = __float2half_rn(o.w - __half2float(h3));
    *(__half2*)(g_xl + base)     = __halves2half2(l0, l1);
    *(__half2*)(g_xl + base + 2) = __halves2half2(l2, l3);
    if (write_f32) *(float4*)(g_x + base) = o;
}

// ---------------- pooling ----------------
__global__ void pool_k(const int* __restrict__ batch, const float* __restrict__ lw) {
    int gt = blockIdx.x * blockDim.x + threadIdx.x;
    int node = gt >> 5;
    int lane = gt & 31;
    if (node >= N_NODES) return;
    float4 xv = ((const float4*)g_x)[node * 32 + lane];
    float4 wv = ((const float4*)lw)[lane];
    float s = xv.x * wv.x + xv.y * wv.y + xv.z * wv.z + xv.w * wv.w;
    #pragma unroll
    for (int o = 16; o > 0; o >>= 1) s += __shfl_xor_sync(0xFFFFFFFFu, s, o);
    if (lane == 0) {
        int g = batch[node];
        atomicAdd(&g_gsum[g], s);
        atomicAdd(&g_gcnt[g], 1);
    }
}

__global__ void final_k(const float* __restrict__ lb, float* __restrict__ out) {
    int g = blockIdx.x * blockDim.x + threadIdx.x;
    if (g >= N_GRAPHS) return;
    float c = fmaxf((float)g_gcnt[g], 1.0f);
    out[g] = g_gsum[g] / c + lb[0];
}

// ---------------- launcher ----------------
extern "C" void kernel_launch(void* const* d_in, const int* in_sizes, int n_in,
                              void* d_out, int out_size) {
    const float* x    = (const float*)d_in[0];
    const int*   ei   = (const int*)d_in[1];    // int32 (JAX x64 disabled)
    const int*   bat  = (const int*)d_in[2];
    const float* Ws   = (const float*)d_in[3];
    const float* bs   = (const float*)d_in[4];
    const float* lw   = (const float*)d_in[5];
    const float* lb   = (const float*)d_in[6];
    float*       out  = (float*)d_out;

    float *h_p;
    __half *xh_p, *xl_p, *wfh_p;
    cudaGetSymbolAddress((void**)&h_p,   g_h);
    cudaGetSymbolAddress((void**)&xh_p,  g_xh);
    cudaGetSymbolAddress((void**)&xl_p,  g_xl);
    cudaGetSymbolAddress((void**)&wfh_p, g_wfh);

    const int gemm_blocks = NROWS / 128;             // 391
    const int gather_blocks = (N_NODES * 32 + 255) / 256;

    // launches 1-3: gemm prerequisites (keeps gemm as launch #4 for ncu)
    wfrag_k<<<(N_LAYERS * D * D + 255) / 256, 256>>>(Ws);
    conv0_k<<<(ND / 2 + 255) / 256, 256>>>(x);
    zero_misc_k<<<(N_NODES + 255) / 256, 256>>>();

    // launch 4: layer-0 GEMM (ncu capture target)
    gemm_tc_k<<<gemm_blocks, 256>>>(
        xh_p, xl_p, (const uint4*)wfh_p, h_p);

    // edge preprocessing (independent of gemm0)
    deg_k<<<(N_EDGES + 255) / 256, 256>>>(ei);
    scan1_k<<<SCAN_NBLK, SCAN_BLK>>>();
    scan2_k<<<1, 32>>>();
    scan3_k<<<(N_NODES + 255) / 256, 256>>>();
    place_k<<<(N_EDGES + 255) / 256, 256>>>(ei);

    // layer 0 gather, then layers 1..2
    gather_k<<<gather_blocks, 256>>>(bs, 0);
    for (int l = 1; l < N_LAYERS; l++) {
        gemm_tc_k<<<gemm_blocks, 256>>>(
            xh_p, xl_p, (const uint4*)(wfh_p + (size_t)l * FRAGH_PER_LAYER), h_p);
        gather_k<<<gather_blocks, 256>>>(bs + l * D, (l == N_LAYERS - 1) ? 1 : 0);
    }

    // pooling + output
    pool_k<<<(N_NODES * 32 + 255) / 256, 256>>>(bat, lw);
    final_k<<<(N_GRAPHS + 255) / 256, 256>>>(lb, out);
}